// round 14
// baseline (speedup 1.0000x reference)
#include <cuda_runtime.h>
#include <cuda_fp16.h>
#include <math.h>
#include <stdint.h>

#define BB 2
#define SS 2048
#define EE 1024
#define HH 16
#define DD 64
#define MM (BB*SS)

// ---------------------------------------------------------------------------
// Scratch (no cudaMalloc allowed)
// ---------------------------------------------------------------------------
__device__ __align__(16) float g_Q[BB*HH*SS*DD];
__device__ __align__(16) float g_K[BB*HH*SS*DD];
__device__ __align__(16) float g_V[BB*HH*SS*DD];
// fp16 fragment-panel buffers
__device__ __align__(16) uint32_t g_Xh[MM/128 * 32 * 2048];     // X  A-panels (2M u32)
__device__ __align__(16) uint32_t g_Ah[MM/128 * 32 * 2048];     // attn-out A-panels
__device__ __align__(16) uint32_t g_Wh[4][EE/128 * 32 * 2048];  // Wq,Wk,Wv,Wo B-panels

// ---------------------------------------------------------------------------
// helpers
// ---------------------------------------------------------------------------
__device__ __forceinline__ uint32_t pack_h2(float lo, float hi) {
    uint32_t u;
    asm("cvt.rn.f16x2.f32 %0, %1, %2;" : "=r"(u) : "f"(hi), "f"(lo));
    return u;
}

__device__ __forceinline__ void mma_f16(float* d, const uint32_t* a, const uint32_t* b) {
    asm volatile(
        "mma.sync.aligned.m16n8k16.row.col.f32.f16.f16.f32 "
        "{%0,%1,%2,%3}, {%4,%5,%6,%7}, {%8,%9}, {%0,%1,%2,%3};\n"
        : "+f"(d[0]), "+f"(d[1]), "+f"(d[2]), "+f"(d[3])
        : "r"(a[0]), "r"(a[1]), "r"(a[2]), "r"(a[3]),
          "r"(b[0]), "r"(b[1]));
}

__device__ __forceinline__ uint32_t smem_u32(const void* p) {
    uint32_t a;
    asm("{ .reg .u64 t; cvta.to.shared.u64 t, %1; cvt.u32.u64 %0, t; }"
        : "=r"(a) : "l"(p));
    return a;
}

__device__ __forceinline__ void cp16(uint32_t saddr, const void* gaddr) {
    asm volatile("cp.async.cg.shared.global [%0], [%1], 16;"
                 :: "r"(saddr), "l"(gaddr));
}
#define CP_COMMIT() asm volatile("cp.async.commit_group;")
#define CP_WAIT2()  asm volatile("cp.async.wait_group 2;")

// A-panel slot for logical (row, col) in [M][K] grid (u32 holds halves col,col+1)
__device__ __forceinline__ int a_slot(int row, int col) {
    int p = (row >> 7) * 32 + (col >> 5);
    int rloc = row & 127, mt = rloc >> 4, r = rloc & 15;
    int kt = (col & 31) >> 4, kl = col & 15;
    return p * 2048 + (mt * 2 + kt) * 128
         + ((r & 7) * 4 + ((kl & 7) >> 1)) * 4 + (r >> 3) + ((kl >> 3) << 1);
}
// B-panel slot for logical (nrow, col) in [N][K]
__device__ __forceinline__ int b_slot(int nrow, int col) {
    int p = (nrow >> 7) * 32 + (col >> 5);
    int nloc = nrow & 127, nt = nloc >> 3, nn = nloc & 7;
    int kt = (col & 31) >> 4, kl = col & 15;
    return p * 2048 + (nt * 2 + kt) * 64
         + (nn * 4 + ((kl & 7) >> 1)) * 2 + (kl >> 3);
}

// [B,H,S,D] scatter address for MODE 1 epilogue
__device__ __forceinline__ float* bhsd_addr(float* out, int row, int col) {
    int b_ = row >> 11;
    int s_ = row & (SS - 1);
    int h_ = col >> 6;
    int d_ = col & (DD - 1);
    return &out[((size_t)(b_ * HH + h_) * SS + s_) * DD + d_];
}

// ---------------------------------------------------------------------------
// cvt kernels: fp32 -> fp16 panels (A-layout for X, B-layout for W's)
// ---------------------------------------------------------------------------
__global__ __launch_bounds__(256) void cvtA_kernel(const float* __restrict__ X,
                                                   uint32_t* __restrict__ dst)
{
    int g = blockIdx.x * 256 + threadIdx.x;   // 0 .. M*K/4
    int row = g >> 8;                         // K/4 = 256
    int c0  = (g & 255) * 4;
    float4 v = *(const float4*)(X + (size_t)row * EE + c0);
    int off = a_slot(row, c0);
    dst[off]     = pack_h2(v.x, v.y);
    dst[off + 4] = pack_h2(v.z, v.w);
}

__global__ __launch_bounds__(256) void cvtB_kernel(
    const float* __restrict__ W0, const float* __restrict__ W1,
    const float* __restrict__ W2, const float* __restrict__ W3)
{
    const float* W = (blockIdx.z == 0) ? W0 : (blockIdx.z == 1) ? W1
                   : (blockIdx.z == 2) ? W2 : W3;
    uint32_t* dst = g_Wh[blockIdx.z];
    int g = blockIdx.x * 256 + threadIdx.x;   // 0 .. N*K/4
    int row = g >> 8;
    int c0  = (g & 255) * 4;
    float4 v = *(const float4*)(W + (size_t)row * EE + c0);
    int off = b_slot(row, c0);
    dst[off]     = pack_h2(v.x, v.y);
    dst[off + 2] = pack_h2(v.z, v.w);
}

// ---------------------------------------------------------------------------
// GEMM v3: fp16 panel inputs, cp.async 4-stage pipeline.
// 256 threads (8 warps), CTA 128x128, warp tile 64x32, K-chunk 32.
// MODE 0: fp32 [M,EE] out.  MODE 1: scatter fp32 [B,H,S,D] (z -> Q/K/V).
// ---------------------------------------------------------------------------
#define GEMM_SMEM3 (4 * 4096 * 4)   // 4 stages x 16KB = 64 KB

template <int MODE>
__global__ __launch_bounds__(256, 2) void gemm_v3(
    const uint32_t* __restrict__ Apan,
    const float* __restrict__ b0, const float* __restrict__ b1,
    const float* __restrict__ b2,
    float* __restrict__ o0, float* __restrict__ o1, float* __restrict__ o2)
{
    extern __shared__ uint32_t sh[];
    const uint32_t sbase = smem_u32(sh);

    const int tid  = threadIdx.x;
    const int lane = tid & 31;
    const int wid  = tid >> 5;
    const int wm   = wid & 1;
    const int wn   = wid >> 1;
    const int zz   = (MODE == 0) ? 3 : blockIdx.z;

    const uint32_t* Bpan = g_Wh[zz];
    const float* bias = (MODE == 0) ? b0 : (blockIdx.z == 0) ? b0
                      : (blockIdx.z == 1) ? b1 : b2;
    float* out = (MODE == 0) ? o0 : (blockIdx.z == 0) ? o0
               : (blockIdx.z == 1) ? o1 : o2;

    const uint4* gAbase = (const uint4*)(Apan + (size_t)blockIdx.y * 32 * 2048);
    const uint4* gBbase = (const uint4*)(Bpan + (size_t)blockIdx.x * 32 * 2048);

    float d[4][4][4];
#pragma unroll
    for (int mt = 0; mt < 4; mt++)
#pragma unroll
        for (int nt = 0; nt < 4; nt++)
#pragma unroll
            for (int e = 0; e < 4; e++) d[mt][nt][e] = 0.f;

    auto issue = [&](int stage, int c) {
        const uint4* gA = gAbase + (size_t)c * 512;
        const uint4* gB = gBbase + (size_t)c * 512;
        uint32_t sA = sbase + stage * 16384;
        uint32_t sB = sA + 8192;
        cp16(sA + tid * 16,         gA + tid);
        cp16(sA + (tid + 256) * 16, gA + tid + 256);
        cp16(sB + tid * 16,         gB + tid);
        cp16(sB + (tid + 256) * 16, gB + tid + 256);
    };

    issue(0, 0); CP_COMMIT();
    issue(1, 1); CP_COMMIT();
    issue(2, 2); CP_COMMIT();

    for (int c = 0; c < 32; c++) {
        CP_WAIT2();
        __syncthreads();

        const uint32_t* sA = sh + (c & 3) * 4096;
        const uint32_t* sB = sA + 2048;
#pragma unroll
        for (int kt = 0; kt < 2; kt++) {
            uint32_t afr[4][4];
            uint32_t bfr[4][2];
#pragma unroll
            for (int mt = 0; mt < 4; mt++)
                *(uint4*)afr[mt] =
                    *(const uint4*)(sA + ((wm * 4 + mt) * 2 + kt) * 128 + lane * 4);
#pragma unroll
            for (int nt = 0; nt < 4; nt++)
                *(uint2*)bfr[nt] =
                    *(const uint2*)(sB + ((wn * 4 + nt) * 2 + kt) * 64 + lane * 2);
#pragma unroll
            for (int mt = 0; mt < 4; mt++)
#pragma unroll
                for (int nt = 0; nt < 4; nt++)
                    mma_f16(d[mt][nt], afr[mt], bfr[nt]);
        }

        if (c + 3 < 32) issue((c + 3) & 3, c + 3);
        CP_COMMIT();    // empty groups in tail iters keep wait accounting uniform
    }

    const int bm = blockIdx.y * 128;
    const int bn = blockIdx.x * 128;
#pragma unroll
    for (int mt = 0; mt < 4; mt++) {
        int row0 = bm + wm * 64 + mt * 16 + (lane >> 2);
#pragma unroll
        for (int nt = 0; nt < 4; nt++) {
            int col = bn + wn * 32 + nt * 8 + (lane & 3) * 2;
            float bx = bias[col], by = bias[col + 1];
            float2 v0 = make_float2(d[mt][nt][0] + bx, d[mt][nt][1] + by);
            float2 v1 = make_float2(d[mt][nt][2] + bx, d[mt][nt][3] + by);
            if (MODE == 0) {
                *(float2*)&out[(size_t)row0 * EE + col] = v0;
                *(float2*)&out[(size_t)(row0 + 8) * EE + col] = v1;
            } else {
                *(float2*)bhsd_addr(out, row0, col) = v0;
                *(float2*)bhsd_addr(out, row0 + 8, col) = v1;
            }
        }
    }
}

// ---------------------------------------------------------------------------
// RoPE on Q and K in [B,H,S,D] layout.
// ---------------------------------------------------------------------------
__global__ void rope_kernel(float* __restrict__ Q, float* __restrict__ K)
{
    int gid = blockIdx.x * blockDim.x + threadIdx.x;
    int i  = gid & 31;
    int s  = (gid >> 5) & (SS - 1);
    int bh = gid >> 16;
    int base = (bh * SS + s) * DD;

    float freq = exp2f(-(float)i * (13.287712379549449f / 32.0f));
    float ang  = (float)s * freq;
    float sn, cs;
    sincosf(ang, &sn, &cs);

    float q0 = Q[base + i], q1 = Q[base + i + 32];
    Q[base + i]      = q0 * cs - q1 * sn;
    Q[base + i + 32] = q1 * cs + q0 * sn;
    float k0 = K[base + i], k1 = K[base + i + 32];
    K[base + i]      = k0 * cs - k1 * sn;
    K[base + i + 32] = k1 * cs + k0 * sn;
}

// ---------------------------------------------------------------------------
// Flash attention (causal), fp16 mma.sync m16n8k16 (validated round 6).
// Epilogue now writes fp16 A-panels (g_Ah) consumed by the O-projection.
// ---------------------------------------------------------------------------
#define ATTN_SMEM_BYTES (3 * 2048 * 4)   // 24 KB

__global__ __launch_bounds__(128) void attn_f16(
    const float* __restrict__ Q, const float* __restrict__ K,
    const float* __restrict__ V, uint32_t* __restrict__ Aout)
{
    extern __shared__ uint32_t su[];
    uint32_t* Qs = su;
    uint32_t* Ks = su + 2048;
    uint32_t* Vs = su + 4096;

    const int tid  = threadIdx.x;
    const int lane = tid & 31;
    const int w    = tid >> 5;

    const int iq = blockIdx.x;
    const int bh = blockIdx.y;
    const int hb = bh * SS * DD;
    const int q0 = iq * 64;

#pragma unroll
    for (int u = 0; u < 8; u++) {
        int idx = tid + u * 128;
        int row = idx >> 4;
        int c0  = (idx & 15) * 4;
        float4 v = *(const float4*)&Q[hb + (q0 + row) * DD + c0];
        int mt = row >> 4, r = row & 15, kt = c0 >> 4, kl = c0 & 15;
        int fi = ((r & 7) * 4 + ((kl & 7) >> 1)) * 4
                 + (r >> 3) + ((kl >> 3) << 1);
        uint32_t* b = Qs + (mt * 4 + kt) * 128 + fi;
        b[0] = pack_h2(v.x * 0.125f, v.y * 0.125f);
        b[4] = pack_h2(v.z * 0.125f, v.w * 0.125f);
    }

    float o[8][4];
#pragma unroll
    for (int nt = 0; nt < 8; nt++)
#pragma unroll
        for (int e = 0; e < 4; e++) o[nt][e] = 0.f;
    float m0 = -1e30f, m1 = -1e30f, l0 = 0.f, l1 = 0.f;

    for (int j = 0; j <= iq; j++) {
        __syncthreads();

#pragma unroll
        for (int u = 0; u < 8; u++) {
            int idx = tid + u * 128;
            int row = idx >> 4;
            int c0  = (idx & 15) * 4;
            float4 kv4 = *(const float4*)&K[hb + (j * 64 + row) * DD + c0];
            int ntile = row >> 3, nn = row & 7, kt = c0 >> 4, kl = c0 & 15;
            int bi = (nn * 4 + ((kl & 7) >> 1)) * 2 + (kl >> 3);
            uint32_t* b = Ks + (ntile * 4 + kt) * 64 + bi;
            b[0] = pack_h2(kv4.x, kv4.y);
            b[2] = pack_h2(kv4.z, kv4.w);
        }
#pragma unroll
        for (int u = 0; u < 4; u++) {
            int idx = tid + u * 128;
            int pr  = idx >> 4;
            int c0  = (idx & 15) * 4;
            int kv0 = pr * 2;
            float4 a4 = *(const float4*)&V[hb + (j * 64 + kv0) * DD + c0];
            float4 b4 = *(const float4*)&V[hb + (j * 64 + kv0 + 1) * DD + c0];
            int kt = kv0 >> 4, kl = kv0 & 15;
            int hp = (kl & 7) >> 1, reg = kl >> 3;
            int ntile = c0 >> 3, nn = c0 & 7;
            uint32_t* b = Vs + (ntile * 4 + kt) * 64;
            b[(nn + 0) * 8 + hp * 2 + reg] = pack_h2(a4.x, b4.x);
            b[(nn + 1) * 8 + hp * 2 + reg] = pack_h2(a4.y, b4.y);
            b[(nn + 2) * 8 + hp * 2 + reg] = pack_h2(a4.z, b4.z);
            b[(nn + 3) * 8 + hp * 2 + reg] = pack_h2(a4.w, b4.w);
        }
        __syncthreads();

        float s[8][4];
#pragma unroll
        for (int nt = 0; nt < 8; nt++)
#pragma unroll
            for (int e = 0; e < 4; e++) s[nt][e] = 0.f;
#pragma unroll
        for (int kt = 0; kt < 4; kt++) {
            uint32_t af[4];
            *(uint4*)af = *(const uint4*)(Qs + (w * 4 + kt) * 128 + lane * 4);
#pragma unroll
            for (int nt = 0; nt < 8; nt++) {
                uint32_t bf[2];
                *(uint2*)bf = *(const uint2*)(Ks + (nt * 4 + kt) * 64 + lane * 2);
                mma_f16(s[nt], af, bf);
            }
        }

        if (j == iq) {
            int lr = w * 16 + (lane >> 2);
#pragma unroll
            for (int nt = 0; nt < 8; nt++) {
                int lc = nt * 8 + (lane & 3) * 2;
                if (lc > lr)     s[nt][0] = -1e30f;
                if (lc + 1 > lr) s[nt][1] = -1e30f;
                if (lc > lr + 8)     s[nt][2] = -1e30f;
                if (lc + 1 > lr + 8) s[nt][3] = -1e30f;
            }
        }

        float mx0 = m0, mx1 = m1;
#pragma unroll
        for (int nt = 0; nt < 8; nt++) {
            mx0 = fmaxf(mx0, fmaxf(s[nt][0], s[nt][1]));
            mx1 = fmaxf(mx1, fmaxf(s[nt][2], s[nt][3]));
        }
        mx0 = fmaxf(mx0, __shfl_xor_sync(0xffffffffu, mx0, 1));
        mx0 = fmaxf(mx0, __shfl_xor_sync(0xffffffffu, mx0, 2));
        mx1 = fmaxf(mx1, __shfl_xor_sync(0xffffffffu, mx1, 1));
        mx1 = fmaxf(mx1, __shfl_xor_sync(0xffffffffu, mx1, 2));
        float corr0 = __expf(m0 - mx0);
        float corr1 = __expf(m1 - mx1);
        m0 = mx0; m1 = mx1;

        uint32_t ap[4][4];
        float lp0 = 0.f, lp1 = 0.f;
#pragma unroll
        for (int nt = 0; nt < 8; nt++) {
            float p00 = __expf(s[nt][0] - mx0);
            float p01 = __expf(s[nt][1] - mx0);
            float p10 = __expf(s[nt][2] - mx1);
            float p11 = __expf(s[nt][3] - mx1);
            lp0 += p00 + p01;
            lp1 += p10 + p11;
            int kt = nt >> 1, h = (nt & 1) * 2;
            ap[kt][h]     = pack_h2(p00, p01);
            ap[kt][h + 1] = pack_h2(p10, p11);
        }
        lp0 += __shfl_xor_sync(0xffffffffu, lp0, 1);
        lp0 += __shfl_xor_sync(0xffffffffu, lp0, 2);
        lp1 += __shfl_xor_sync(0xffffffffu, lp1, 1);
        lp1 += __shfl_xor_sync(0xffffffffu, lp1, 2);
        l0 = l0 * corr0 + lp0;
        l1 = l1 * corr1 + lp1;

#pragma unroll
        for (int nt = 0; nt < 8; nt++) {
            o[nt][0] *= corr0; o[nt][1] *= corr0;
            o[nt][2] *= corr1; o[nt][3] *= corr1;
        }

#pragma unroll
        for (int kt = 0; kt < 4; kt++) {
#pragma unroll
            for (int nt = 0; nt < 8; nt++) {
                uint32_t bf[2];
                *(uint2*)bf = *(const uint2*)(Vs + (nt * 4 + kt) * 64 + lane * 2);
                mma_f16(o[nt], ap[kt], bf);
            }
        }
    }

    // ---- normalize + write fp16 A-panels ----
    float inv0 = 1.f / l0;
    float inv1 = 1.f / l1;
    int b_ = bh >> 4;
    int h_ = bh & 15;
    int grow = b_ * SS + q0 + w * 16 + (lane >> 2);
#pragma unroll
    for (int nt = 0; nt < 8; nt++) {
        int col = h_ * DD + nt * 8 + (lane & 3) * 2;
        Aout[a_slot(grow, col)]     = pack_h2(o[nt][0] * inv0, o[nt][1] * inv0);
        Aout[a_slot(grow + 8, col)] = pack_h2(o[nt][2] * inv1, o[nt][3] * inv1);
    }
}

// ---------------------------------------------------------------------------
extern "C" void kernel_launch(void* const* d_in, const int* in_sizes, int n_in,
                              void* d_out, int out_size)
{
    const float* x  = (const float*)d_in[0];
    // d_in[1] = mask (causal; structure known statically, unused)
    const float* Wq = (const float*)d_in[2];
    const float* bq = (const float*)d_in[3];
    const float* Wk = (const float*)d_in[4];
    const float* bk = (const float*)d_in[5];
    const float* Wv = (const float*)d_in[6];
    const float* bv = (const float*)d_in[7];
    const float* Wo = (const float*)d_in[8];
    const float* bo = (const float*)d_in[9];

    float *Qp, *Kp, *Vp;
    uint32_t *Xh, *Ah;
    cudaGetSymbolAddress((void**)&Qp, g_Q);
    cudaGetSymbolAddress((void**)&Kp, g_K);
    cudaGetSymbolAddress((void**)&Vp, g_V);
    cudaGetSymbolAddress((void**)&Xh, g_Xh);
    cudaGetSymbolAddress((void**)&Ah, g_Ah);

    cudaFuncSetAttribute(gemm_v3<0>,
                         cudaFuncAttributeMaxDynamicSharedMemorySize, GEMM_SMEM3);
    cudaFuncSetAttribute(gemm_v3<1>,
                         cudaFuncAttributeMaxDynamicSharedMemorySize, GEMM_SMEM3);
    cudaFuncSetAttribute(attn_f16,
                         cudaFuncAttributeMaxDynamicSharedMemorySize, ATTN_SMEM_BYTES);

    // fp32 -> fp16 panel conversions
    cvtA_kernel<<<MM * EE / 4 / 256, 256>>>(x, Xh);
    cvtB_kernel<<<dim3(EE * EE / 4 / 256, 1, 4), 256>>>(Wq, Wk, Wv, Wo);

    // QKV fused (z selects W panel / bias / output)
    gemm_v3<1><<<dim3(EE / 128, MM / 128, 3), 256, GEMM_SMEM3>>>(
        Xh, bq, bk, bv, Qp, Kp, Vp);

    rope_kernel<<<(BB * HH * SS * 32) / 256, 256>>>(Qp, Kp);

    attn_f16<<<dim3(SS / 64, BB * HH), 128, ATTN_SMEM_BYTES>>>(Qp, Kp, Vp, Ah);

    // Output projection (uses Wo panel = g_Wh[3])
    gemm_v3<0><<<dim3(EE / 128, MM / 128, 1), 256, GEMM_SMEM3>>>(
        Ah, bo, bo, bo, (float*)d_out, nullptr, nullptr);
}

// round 15
// speedup vs baseline: 1.5865x; 1.5865x over previous
#include <cuda_runtime.h>
#include <cuda_fp16.h>
#include <math.h>
#include <stdint.h>

#define BB 2
#define SS 2048
#define EE 1024
#define HH 16
#define DD 64
#define MM (BB*SS)

// ---------------------------------------------------------------------------
// Scratch (no cudaMalloc allowed)
// ---------------------------------------------------------------------------
__device__ __align__(16) float g_Q[BB*HH*SS*DD];
__device__ __align__(16) float g_K[BB*HH*SS*DD];
__device__ __align__(16) float g_V[BB*HH*SS*DD];
// fp16 fragment-panel buffers
__device__ __align__(16) uint32_t g_Xh[MM/128 * 32 * 2048];     // X  A-panels
__device__ __align__(16) uint32_t g_Ah[MM/128 * 32 * 2048];     // attn-out A-panels
__device__ __align__(16) uint32_t g_Wh[4][EE/128 * 32 * 2048];  // Wq,Wk,Wv,Wo B-panels

// ---------------------------------------------------------------------------
// helpers
// ---------------------------------------------------------------------------
__device__ __forceinline__ uint32_t pack_h2(float lo, float hi) {
    uint32_t u;
    asm("cvt.rn.f16x2.f32 %0, %1, %2;" : "=r"(u) : "f"(hi), "f"(lo));
    return u;
}

__device__ __forceinline__ void mma_f16(float* d, const uint32_t* a, const uint32_t* b) {
    asm volatile(
        "mma.sync.aligned.m16n8k16.row.col.f32.f16.f16.f32 "
        "{%0,%1,%2,%3}, {%4,%5,%6,%7}, {%8,%9}, {%0,%1,%2,%3};\n"
        : "+f"(d[0]), "+f"(d[1]), "+f"(d[2]), "+f"(d[3])
        : "r"(a[0]), "r"(a[1]), "r"(a[2]), "r"(a[3]),
          "r"(b[0]), "r"(b[1]));
}

__device__ __forceinline__ uint32_t smem_u32(const void* p) {
    uint32_t a;
    asm("{ .reg .u64 t; cvta.to.shared.u64 t, %1; cvt.u32.u64 %0, t; }"
        : "=r"(a) : "l"(p));
    return a;
}

__device__ __forceinline__ void cp16(uint32_t saddr, const void* gaddr) {
    asm volatile("cp.async.cg.shared.global [%0], [%1], 16;"
                 :: "r"(saddr), "l"(gaddr));
}
#define CP_COMMIT() asm volatile("cp.async.commit_group;")
#define CP_WAIT2()  asm volatile("cp.async.wait_group 2;")

// A-panel slot for logical (row, col) in [M][K] grid (u32 holds halves col,col+1)
__device__ __forceinline__ int a_slot(int row, int col) {
    int p = (row >> 7) * 32 + (col >> 5);
    int rloc = row & 127, mt = rloc >> 4, r = rloc & 15;
    int kt = (col & 31) >> 4, kl = col & 15;
    return p * 2048 + (mt * 2 + kt) * 128
         + ((r & 7) * 4 + ((kl & 7) >> 1)) * 4 + (r >> 3) + ((kl >> 3) << 1);
}
// B-panel slot for logical (nrow, col) in [N][K]
__device__ __forceinline__ int b_slot(int nrow, int col) {
    int p = (nrow >> 7) * 32 + (col >> 5);
    int nloc = nrow & 127, nt = nloc >> 3, nn = nloc & 7;
    int kt = (col & 31) >> 4, kl = col & 15;
    return p * 2048 + (nt * 2 + kt) * 64
         + (nn * 4 + ((kl & 7) >> 1)) * 2 + (kl >> 3);
}

// [B,H,S,D] scatter address for MODE 1 epilogue
__device__ __forceinline__ float* bhsd_addr(float* out, int row, int col) {
    int b_ = row >> 11;
    int s_ = row & (SS - 1);
    int h_ = col >> 6;
    int d_ = col & (DD - 1);
    return &out[((size_t)(b_ * HH + h_) * SS + s_) * DD + d_];
}

// ---------------------------------------------------------------------------
// cvt kernels: fp32 -> fp16 panels (A-layout for X, B-layout for W's)
// ---------------------------------------------------------------------------
__global__ __launch_bounds__(256) void cvtA_kernel(const float* __restrict__ X,
                                                   uint32_t* __restrict__ dst)
{
    int g = blockIdx.x * 256 + threadIdx.x;
    int row = g >> 8;
    int c0  = (g & 255) * 4;
    float4 v = *(const float4*)(X + (size_t)row * EE + c0);
    int off = a_slot(row, c0);
    dst[off]     = pack_h2(v.x, v.y);
    dst[off + 4] = pack_h2(v.z, v.w);
}

__global__ __launch_bounds__(256) void cvtB_kernel(
    const float* __restrict__ W0, const float* __restrict__ W1,
    const float* __restrict__ W2, const float* __restrict__ W3)
{
    const float* W = (blockIdx.z == 0) ? W0 : (blockIdx.z == 1) ? W1
                   : (blockIdx.z == 2) ? W2 : W3;
    uint32_t* dst = g_Wh[blockIdx.z];
    int g = blockIdx.x * 256 + threadIdx.x;
    int row = g >> 8;
    int c0  = (g & 255) * 4;
    float4 v = *(const float4*)(W + (size_t)row * EE + c0);
    int off = b_slot(row, c0);
    dst[off]     = pack_h2(v.x, v.y);
    dst[off + 2] = pack_h2(v.z, v.w);
}

// ---------------------------------------------------------------------------
// GEMM v4: fp16 panel inputs + cp.async 4-stage + 64x64 warp tiles.
// 128 threads (4 warps), CTA 128x128, warp tile 64x64 (mt 0..3, nt 0..7),
// K-chunk 32 (2 k16 steps).  MODE 0: fp32 [M,EE] out.
// MODE 1: scatter fp32 [B,H,S,D] (blockIdx.z -> Q/K/V).
// ---------------------------------------------------------------------------
#define GEMM_SMEM4 (4 * 4096 * 4)   // 4 stages x 16KB = 64 KB

template <int MODE>
__global__ __launch_bounds__(128, 2) void gemm_v4(
    const uint32_t* __restrict__ Apan,
    const float* __restrict__ b0, const float* __restrict__ b1,
    const float* __restrict__ b2,
    float* __restrict__ o0, float* __restrict__ o1, float* __restrict__ o2)
{
    extern __shared__ uint32_t sh[];
    const uint32_t sbase = smem_u32(sh);

    const int tid  = threadIdx.x;
    const int lane = tid & 31;
    const int wid  = tid >> 5;
    const int wm   = wid & 1;          // 64-row half
    const int wn   = wid >> 1;         // 64-col half
    const int zz   = (MODE == 0) ? 3 : blockIdx.z;

    const uint32_t* Bpan = g_Wh[zz];
    const float* bias = (MODE == 0) ? b0 : (blockIdx.z == 0) ? b0
                      : (blockIdx.z == 1) ? b1 : b2;
    float* out = (MODE == 0) ? o0 : (blockIdx.z == 0) ? o0
               : (blockIdx.z == 1) ? o1 : o2;

    const uint4* gAbase = (const uint4*)(Apan + (size_t)blockIdx.y * 32 * 2048);
    const uint4* gBbase = (const uint4*)(Bpan + (size_t)blockIdx.x * 32 * 2048);

    float d[4][8][4];
#pragma unroll
    for (int mt = 0; mt < 4; mt++)
#pragma unroll
        for (int nt = 0; nt < 8; nt++)
#pragma unroll
            for (int e = 0; e < 4; e++) d[mt][nt][e] = 0.f;

    // 1024 uint4 per chunk (A 512 + B 512); 8 cp16 per thread
    auto issue = [&](int stage, int c) {
        const uint4* gA = gAbase + (size_t)c * 512;
        const uint4* gB = gBbase + (size_t)c * 512;
        uint32_t sA = sbase + stage * 16384;
        uint32_t sB = sA + 8192;
#pragma unroll
        for (int u = 0; u < 4; u++) {
            cp16(sA + (tid + u * 128) * 16, gA + tid + u * 128);
            cp16(sB + (tid + u * 128) * 16, gB + tid + u * 128);
        }
    };

    issue(0, 0); CP_COMMIT();
    issue(1, 1); CP_COMMIT();
    issue(2, 2); CP_COMMIT();

    for (int c = 0; c < 32; c++) {
        CP_WAIT2();
        __syncthreads();

        const uint32_t* sA = sh + (c & 3) * 4096;
        const uint32_t* sB = sA + 2048;
#pragma unroll
        for (int kt = 0; kt < 2; kt++) {
            uint32_t afr[4][4];
            uint32_t bfr[8][2];
#pragma unroll
            for (int mt = 0; mt < 4; mt++)
                *(uint4*)afr[mt] =
                    *(const uint4*)(sA + ((wm * 4 + mt) * 2 + kt) * 128 + lane * 4);
#pragma unroll
            for (int nt = 0; nt < 8; nt++)
                *(uint2*)bfr[nt] =
                    *(const uint2*)(sB + ((wn * 8 + nt) * 2 + kt) * 64 + lane * 2);
#pragma unroll
            for (int mt = 0; mt < 4; mt++)
#pragma unroll
                for (int nt = 0; nt < 8; nt++)
                    mma_f16(d[mt][nt], afr[mt], bfr[nt]);
        }

        if (c + 3 < 32) issue((c + 3) & 3, c + 3);
        CP_COMMIT();    // empty groups in tail keep wait accounting uniform
    }

    const int bm = blockIdx.y * 128;
    const int bn = blockIdx.x * 128;
#pragma unroll
    for (int mt = 0; mt < 4; mt++) {
        int row0 = bm + wm * 64 + mt * 16 + (lane >> 2);
#pragma unroll
        for (int nt = 0; nt < 8; nt++) {
            int col = bn + wn * 64 + nt * 8 + (lane & 3) * 2;
            float bx = bias[col], by = bias[col + 1];
            float2 v0 = make_float2(d[mt][nt][0] + bx, d[mt][nt][1] + by);
            float2 v1 = make_float2(d[mt][nt][2] + bx, d[mt][nt][3] + by);
            if (MODE == 0) {
                *(float2*)&out[(size_t)row0 * EE + col] = v0;
                *(float2*)&out[(size_t)(row0 + 8) * EE + col] = v1;
            } else {
                *(float2*)bhsd_addr(out, row0, col) = v0;
                *(float2*)bhsd_addr(out, row0 + 8, col) = v1;
            }
        }
    }
}

// ---------------------------------------------------------------------------
// RoPE on Q and K in [B,H,S,D] layout.
// ---------------------------------------------------------------------------
__global__ void rope_kernel(float* __restrict__ Q, float* __restrict__ K)
{
    int gid = blockIdx.x * blockDim.x + threadIdx.x;
    int i  = gid & 31;
    int s  = (gid >> 5) & (SS - 1);
    int bh = gid >> 16;
    int base = (bh * SS + s) * DD;

    float freq = exp2f(-(float)i * (13.287712379549449f / 32.0f));
    float ang  = (float)s * freq;
    float sn, cs;
    sincosf(ang, &sn, &cs);

    float q0 = Q[base + i], q1 = Q[base + i + 32];
    Q[base + i]      = q0 * cs - q1 * sn;
    Q[base + i + 32] = q1 * cs + q0 * sn;
    float k0 = K[base + i], k1 = K[base + i + 32];
    K[base + i]      = k0 * cs - k1 * sn;
    K[base + i + 32] = k1 * cs + k0 * sn;
}

// ---------------------------------------------------------------------------
// Flash attention (causal), fp16 mma.sync m16n8k16 (validated round 6).
// Epilogue writes fp16 A-panels (g_Ah) consumed by the O-projection.
// ---------------------------------------------------------------------------
#define ATTN_SMEM_BYTES (3 * 2048 * 4)   // 24 KB

__global__ __launch_bounds__(128) void attn_f16(
    const float* __restrict__ Q, const float* __restrict__ K,
    const float* __restrict__ V, uint32_t* __restrict__ Aout)
{
    extern __shared__ uint32_t su[];
    uint32_t* Qs = su;
    uint32_t* Ks = su + 2048;
    uint32_t* Vs = su + 4096;

    const int tid  = threadIdx.x;
    const int lane = tid & 31;
    const int w    = tid >> 5;

    const int iq = blockIdx.x;
    const int bh = blockIdx.y;
    const int hb = bh * SS * DD;
    const int q0 = iq * 64;

#pragma unroll
    for (int u = 0; u < 8; u++) {
        int idx = tid + u * 128;
        int row = idx >> 4;
        int c0  = (idx & 15) * 4;
        float4 v = *(const float4*)&Q[hb + (q0 + row) * DD + c0];
        int mt = row >> 4, r = row & 15, kt = c0 >> 4, kl = c0 & 15;
        int fi = ((r & 7) * 4 + ((kl & 7) >> 1)) * 4
                 + (r >> 3) + ((kl >> 3) << 1);
        uint32_t* b = Qs + (mt * 4 + kt) * 128 + fi;
        b[0] = pack_h2(v.x * 0.125f, v.y * 0.125f);
        b[4] = pack_h2(v.z * 0.125f, v.w * 0.125f);
    }

    float o[8][4];
#pragma unroll
    for (int nt = 0; nt < 8; nt++)
#pragma unroll
        for (int e = 0; e < 4; e++) o[nt][e] = 0.f;
    float m0 = -1e30f, m1 = -1e30f, l0 = 0.f, l1 = 0.f;

    for (int j = 0; j <= iq; j++) {
        __syncthreads();

#pragma unroll
        for (int u = 0; u < 8; u++) {
            int idx = tid + u * 128;
            int row = idx >> 4;
            int c0  = (idx & 15) * 4;
            float4 kv4 = *(const float4*)&K[hb + (j * 64 + row) * DD + c0];
            int ntile = row >> 3, nn = row & 7, kt = c0 >> 4, kl = c0 & 15;
            int bi = (nn * 4 + ((kl & 7) >> 1)) * 2 + (kl >> 3);
            uint32_t* b = Ks + (ntile * 4 + kt) * 64 + bi;
            b[0] = pack_h2(kv4.x, kv4.y);
            b[2] = pack_h2(kv4.z, kv4.w);
        }
#pragma unroll
        for (int u = 0; u < 4; u++) {
            int idx = tid + u * 128;
            int pr  = idx >> 4;
            int c0  = (idx & 15) * 4;
            int kv0 = pr * 2;
            float4 a4 = *(const float4*)&V[hb + (j * 64 + kv0) * DD + c0];
            float4 b4 = *(const float4*)&V[hb + (j * 64 + kv0 + 1) * DD + c0];
            int kt = kv0 >> 4, kl = kv0 & 15;
            int hp = (kl & 7) >> 1, reg = kl >> 3;
            int ntile = c0 >> 3, nn = c0 & 7;
            uint32_t* b = Vs + (ntile * 4 + kt) * 64;
            b[(nn + 0) * 8 + hp * 2 + reg] = pack_h2(a4.x, b4.x);
            b[(nn + 1) * 8 + hp * 2 + reg] = pack_h2(a4.y, b4.y);
            b[(nn + 2) * 8 + hp * 2 + reg] = pack_h2(a4.z, b4.z);
            b[(nn + 3) * 8 + hp * 2 + reg] = pack_h2(a4.w, b4.w);
        }
        __syncthreads();

        float s[8][4];
#pragma unroll
        for (int nt = 0; nt < 8; nt++)
#pragma unroll
            for (int e = 0; e < 4; e++) s[nt][e] = 0.f;
#pragma unroll
        for (int kt = 0; kt < 4; kt++) {
            uint32_t af[4];
            *(uint4*)af = *(const uint4*)(Qs + (w * 4 + kt) * 128 + lane * 4);
#pragma unroll
            for (int nt = 0; nt < 8; nt++) {
                uint32_t bf[2];
                *(uint2*)bf = *(const uint2*)(Ks + (nt * 4 + kt) * 64 + lane * 2);
                mma_f16(s[nt], af, bf);
            }
        }

        if (j == iq) {
            int lr = w * 16 + (lane >> 2);
#pragma unroll
            for (int nt = 0; nt < 8; nt++) {
                int lc = nt * 8 + (lane & 3) * 2;
                if (lc > lr)     s[nt][0] = -1e30f;
                if (lc + 1 > lr) s[nt][1] = -1e30f;
                if (lc > lr + 8)     s[nt][2] = -1e30f;
                if (lc + 1 > lr + 8) s[nt][3] = -1e30f;
            }
        }

        float mx0 = m0, mx1 = m1;
#pragma unroll
        for (int nt = 0; nt < 8; nt++) {
            mx0 = fmaxf(mx0, fmaxf(s[nt][0], s[nt][1]));
            mx1 = fmaxf(mx1, fmaxf(s[nt][2], s[nt][3]));
        }
        mx0 = fmaxf(mx0, __shfl_xor_sync(0xffffffffu, mx0, 1));
        mx0 = fmaxf(mx0, __shfl_xor_sync(0xffffffffu, mx0, 2));
        mx1 = fmaxf(mx1, __shfl_xor_sync(0xffffffffu, mx1, 1));
        mx1 = fmaxf(mx1, __shfl_xor_sync(0xffffffffu, mx1, 2));
        float corr0 = __expf(m0 - mx0);
        float corr1 = __expf(m1 - mx1);
        m0 = mx0; m1 = mx1;

        uint32_t ap[4][4];
        float lp0 = 0.f, lp1 = 0.f;
#pragma unroll
        for (int nt = 0; nt < 8; nt++) {
            float p00 = __expf(s[nt][0] - mx0);
            float p01 = __expf(s[nt][1] - mx0);
            float p10 = __expf(s[nt][2] - mx1);
            float p11 = __expf(s[nt][3] - mx1);
            lp0 += p00 + p01;
            lp1 += p10 + p11;
            int kt = nt >> 1, h = (nt & 1) * 2;
            ap[kt][h]     = pack_h2(p00, p01);
            ap[kt][h + 1] = pack_h2(p10, p11);
        }
        lp0 += __shfl_xor_sync(0xffffffffu, lp0, 1);
        lp0 += __shfl_xor_sync(0xffffffffu, lp0, 2);
        lp1 += __shfl_xor_sync(0xffffffffu, lp1, 1);
        lp1 += __shfl_xor_sync(0xffffffffu, lp1, 2);
        l0 = l0 * corr0 + lp0;
        l1 = l1 * corr1 + lp1;

#pragma unroll
        for (int nt = 0; nt < 8; nt++) {
            o[nt][0] *= corr0; o[nt][1] *= corr0;
            o[nt][2] *= corr1; o[nt][3] *= corr1;
        }

#pragma unroll
        for (int kt = 0; kt < 4; kt++) {
#pragma unroll
            for (int nt = 0; nt < 8; nt++) {
                uint32_t bf[2];
                *(uint2*)bf = *(const uint2*)(Vs + (nt * 4 + kt) * 64 + lane * 2);
                mma_f16(o[nt], ap[kt], bf);
            }
        }
    }

    // ---- normalize + write fp16 A-panels ----
    float inv0 = 1.f / l0;
    float inv1 = 1.f / l1;
    int b_ = bh >> 4;
    int h_ = bh & 15;
    int grow = b_ * SS + q0 + w * 16 + (lane >> 2);
#pragma unroll
    for (int nt = 0; nt < 8; nt++) {
        int col = h_ * DD + nt * 8 + (lane & 3) * 2;
        Aout[a_slot(grow, col)]     = pack_h2(o[nt][0] * inv0, o[nt][1] * inv0);
        Aout[a_slot(grow + 8, col)] = pack_h2(o[nt][2] * inv1, o[nt][3] * inv1);
    }
}

// ---------------------------------------------------------------------------
extern "C" void kernel_launch(void* const* d_in, const int* in_sizes, int n_in,
                              void* d_out, int out_size)
{
    const float* x  = (const float*)d_in[0];
    // d_in[1] = mask (causal; structure known statically, unused)
    const float* Wq = (const float*)d_in[2];
    const float* bq = (const float*)d_in[3];
    const float* Wk = (const float*)d_in[4];
    const float* bk = (const float*)d_in[5];
    const float* Wv = (const float*)d_in[6];
    const float* bv = (const float*)d_in[7];
    const float* Wo = (const float*)d_in[8];
    const float* bo = (const float*)d_in[9];

    float *Qp, *Kp, *Vp;
    uint32_t *Xh, *Ah;
    cudaGetSymbolAddress((void**)&Qp, g_Q);
    cudaGetSymbolAddress((void**)&Kp, g_K);
    cudaGetSymbolAddress((void**)&Vp, g_V);
    cudaGetSymbolAddress((void**)&Xh, g_Xh);
    cudaGetSymbolAddress((void**)&Ah, g_Ah);

    cudaFuncSetAttribute(gemm_v4<0>,
                         cudaFuncAttributeMaxDynamicSharedMemorySize, GEMM_SMEM4);
    cudaFuncSetAttribute(gemm_v4<1>,
                         cudaFuncAttributeMaxDynamicSharedMemorySize, GEMM_SMEM4);
    cudaFuncSetAttribute(attn_f16,
                         cudaFuncAttributeMaxDynamicSharedMemorySize, ATTN_SMEM_BYTES);

    // fp32 -> fp16 panel conversions
    cvtA_kernel<<<MM * EE / 4 / 256, 256>>>(x, Xh);
    cvtB_kernel<<<dim3(EE * EE / 4 / 256, 1, 4), 256>>>(Wq, Wk, Wv, Wo);

    // QKV fused (z selects W panel / bias / output)
    gemm_v4<1><<<dim3(EE / 128, MM / 128, 3), 128, GEMM_SMEM4>>>(
        Xh, bq, bk, bv, Qp, Kp, Vp);

    rope_kernel<<<(BB * HH * SS * 32) / 256, 256>>>(Qp, Kp);

    attn_f16<<<dim3(SS / 64, BB * HH), 128, ATTN_SMEM_BYTES>>>(Qp, Kp, Vp, Ah);

    // Output projection (uses Wo panel = g_Wh[3])
    gemm_v4<0><<<dim3(EE / 128, MM / 128, 1), 128, GEMM_SMEM4>>>(
        Ah, bo, bo, bo, (float*)d_out, nullptr, nullptr);
}

// round 16
// speedup vs baseline: 2.4373x; 1.5362x over previous
#include <cuda_runtime.h>
#include <cuda_fp16.h>
#include <math.h>
#include <stdint.h>

#define BB 2
#define SS 2048
#define EE 1024
#define HH 16
#define DD 64
#define MM (BB*SS)

// ---------------------------------------------------------------------------
// Scratch (no cudaMalloc allowed)
// ---------------------------------------------------------------------------
__device__ __align__(16) float g_Q[BB*HH*SS*DD];
__device__ __align__(16) float g_K[BB*HH*SS*DD];
__device__ __align__(16) float g_V[BB*HH*SS*DD];
// fp16 fragment-panel buffers
__device__ __align__(16) uint32_t g_Xh[MM/128 * 32 * 2048];     // X  A-panels
__device__ __align__(16) uint32_t g_Ah[MM/128 * 32 * 2048];     // attn-out A-panels
__device__ __align__(16) uint32_t g_Wh[4][EE/128 * 32 * 2048];  // Wq,Wk,Wv,Wo B-panels
// attention fp16 panels: [bh][tile][2048]
__device__ __align__(16) uint32_t g_Qh[32 * 32 * 2048];
__device__ __align__(16) uint32_t g_Kh[32 * 32 * 2048];
__device__ __align__(16) uint32_t g_Vh[32 * 32 * 2048];

// ---------------------------------------------------------------------------
// helpers
// ---------------------------------------------------------------------------
__device__ __forceinline__ uint32_t pack_h2(float lo, float hi) {
    uint32_t u;
    asm("cvt.rn.f16x2.f32 %0, %1, %2;" : "=r"(u) : "f"(hi), "f"(lo));
    return u;
}

__device__ __forceinline__ void mma_f16(float* d, const uint32_t* a, const uint32_t* b) {
    asm volatile(
        "mma.sync.aligned.m16n8k16.row.col.f32.f16.f16.f32 "
        "{%0,%1,%2,%3}, {%4,%5,%6,%7}, {%8,%9}, {%0,%1,%2,%3};\n"
        : "+f"(d[0]), "+f"(d[1]), "+f"(d[2]), "+f"(d[3])
        : "r"(a[0]), "r"(a[1]), "r"(a[2]), "r"(a[3]),
          "r"(b[0]), "r"(b[1]));
}

__device__ __forceinline__ uint32_t smem_u32(const void* p) {
    uint32_t a;
    asm("{ .reg .u64 t; cvta.to.shared.u64 t, %1; cvt.u32.u64 %0, t; }"
        : "=r"(a) : "l"(p));
    return a;
}

__device__ __forceinline__ void cp16(uint32_t saddr, const void* gaddr) {
    asm volatile("cp.async.cg.shared.global [%0], [%1], 16;"
                 :: "r"(saddr), "l"(gaddr));
}
#define CP_COMMIT() asm volatile("cp.async.commit_group;")
#define CP_WAIT2()  asm volatile("cp.async.wait_group 2;")
#define CP_WAIT0()  asm volatile("cp.async.wait_group 0;")

// A-panel slot for logical (row, col) in [M][K] grid (u32 holds halves col,col+1)
__device__ __forceinline__ int a_slot(int row, int col) {
    int p = (row >> 7) * 32 + (col >> 5);
    int rloc = row & 127, mt = rloc >> 4, r = rloc & 15;
    int kt = (col & 31) >> 4, kl = col & 15;
    return p * 2048 + (mt * 2 + kt) * 128
         + ((r & 7) * 4 + ((kl & 7) >> 1)) * 4 + (r >> 3) + ((kl >> 3) << 1);
}
// B-panel slot for logical (nrow, col) in [N][K]
__device__ __forceinline__ int b_slot(int nrow, int col) {
    int p = (nrow >> 7) * 32 + (col >> 5);
    int nloc = nrow & 127, nt = nloc >> 3, nn = nloc & 7;
    int kt = (col & 31) >> 4, kl = col & 15;
    return p * 2048 + (nt * 2 + kt) * 64
         + (nn * 4 + ((kl & 7) >> 1)) * 2 + (kl >> 3);
}

// attention per-tile slots (tile-local, 2048 u32)
__device__ __forceinline__ int q_slot(int row, int d) {   // A-frag, row 0..63
    int mt = row >> 4, r = row & 15, kt = d >> 4, kl = d & 15;
    return (mt * 4 + kt) * 128 + ((r & 7) * 4 + ((kl & 7) >> 1)) * 4
         + (r >> 3) + ((kl >> 3) << 1);
}
__device__ __forceinline__ int kv_slot(int n, int k) {    // B-frag, n 0..63, k 0..63
    int nt = n >> 3, nn = n & 7, kt = k >> 4, kl = k & 15;
    return (nt * 4 + kt) * 64 + nn * 8 + ((kl & 7) >> 1) * 2 + (kl >> 3);
}

// [B,H,S,D] scatter address for MODE 1 epilogue
__device__ __forceinline__ float* bhsd_addr(float* out, int row, int col) {
    int b_ = row >> 11;
    int s_ = row & (SS - 1);
    int h_ = col >> 6;
    int d_ = col & (DD - 1);
    return &out[((size_t)(b_ * HH + h_) * SS + s_) * DD + d_];
}

// ---------------------------------------------------------------------------
// cvt kernels: fp32 -> fp16 panels (A-layout for X, B-layout for W's)
// ---------------------------------------------------------------------------
__global__ __launch_bounds__(256) void cvtA_kernel(const float* __restrict__ X,
                                                   uint32_t* __restrict__ dst)
{
    int g = blockIdx.x * 256 + threadIdx.x;
    int row = g >> 8;
    int c0  = (g & 255) * 4;
    float4 v = *(const float4*)(X + (size_t)row * EE + c0);
    int off = a_slot(row, c0);
    dst[off]     = pack_h2(v.x, v.y);
    dst[off + 4] = pack_h2(v.z, v.w);
}

__global__ __launch_bounds__(256) void cvtB_kernel(
    const float* __restrict__ W0, const float* __restrict__ W1,
    const float* __restrict__ W2, const float* __restrict__ W3)
{
    const float* W = (blockIdx.z == 0) ? W0 : (blockIdx.z == 1) ? W1
                   : (blockIdx.z == 2) ? W2 : W3;
    uint32_t* dst = g_Wh[blockIdx.z];
    int g = blockIdx.x * 256 + threadIdx.x;
    int row = g >> 8;
    int c0  = (g & 255) * 4;
    float4 v = *(const float4*)(W + (size_t)row * EE + c0);
    int off = b_slot(row, c0);
    dst[off]     = pack_h2(v.x, v.y);
    dst[off + 2] = pack_h2(v.z, v.w);
}

// ---------------------------------------------------------------------------
// GEMM v4 (validated round 15): fp16 panels + cp.async 4-stage + 64x64 wtiles.
// ---------------------------------------------------------------------------
#define GEMM_SMEM4 (4 * 4096 * 4)   // 64 KB

template <int MODE>
__global__ __launch_bounds__(128, 2) void gemm_v4(
    const uint32_t* __restrict__ Apan,
    const float* __restrict__ b0, const float* __restrict__ b1,
    const float* __restrict__ b2,
    float* __restrict__ o0, float* __restrict__ o1, float* __restrict__ o2)
{
    extern __shared__ uint32_t sh[];
    const uint32_t sbase = smem_u32(sh);

    const int tid  = threadIdx.x;
    const int lane = tid & 31;
    const int wid  = tid >> 5;
    const int wm   = wid & 1;
    const int wn   = wid >> 1;
    const int zz   = (MODE == 0) ? 3 : blockIdx.z;

    const uint32_t* Bpan = g_Wh[zz];
    const float* bias = (MODE == 0) ? b0 : (blockIdx.z == 0) ? b0
                      : (blockIdx.z == 1) ? b1 : b2;
    float* out = (MODE == 0) ? o0 : (blockIdx.z == 0) ? o0
               : (blockIdx.z == 1) ? o1 : o2;

    const uint4* gAbase = (const uint4*)(Apan + (size_t)blockIdx.y * 32 * 2048);
    const uint4* gBbase = (const uint4*)(Bpan + (size_t)blockIdx.x * 32 * 2048);

    float d[4][8][4];
#pragma unroll
    for (int mt = 0; mt < 4; mt++)
#pragma unroll
        for (int nt = 0; nt < 8; nt++)
#pragma unroll
            for (int e = 0; e < 4; e++) d[mt][nt][e] = 0.f;

    auto issue = [&](int stage, int c) {
        const uint4* gA = gAbase + (size_t)c * 512;
        const uint4* gB = gBbase + (size_t)c * 512;
        uint32_t sA = sbase + stage * 16384;
        uint32_t sB = sA + 8192;
#pragma unroll
        for (int u = 0; u < 4; u++) {
            cp16(sA + (tid + u * 128) * 16, gA + tid + u * 128);
            cp16(sB + (tid + u * 128) * 16, gB + tid + u * 128);
        }
    };

    issue(0, 0); CP_COMMIT();
    issue(1, 1); CP_COMMIT();
    issue(2, 2); CP_COMMIT();

    for (int c = 0; c < 32; c++) {
        CP_WAIT2();
        __syncthreads();

        const uint32_t* sA = sh + (c & 3) * 4096;
        const uint32_t* sB = sA + 2048;
#pragma unroll
        for (int kt = 0; kt < 2; kt++) {
            uint32_t afr[4][4];
            uint32_t bfr[8][2];
#pragma unroll
            for (int mt = 0; mt < 4; mt++)
                *(uint4*)afr[mt] =
                    *(const uint4*)(sA + ((wm * 4 + mt) * 2 + kt) * 128 + lane * 4);
#pragma unroll
            for (int nt = 0; nt < 8; nt++)
                *(uint2*)bfr[nt] =
                    *(const uint2*)(sB + ((wn * 8 + nt) * 2 + kt) * 64 + lane * 2);
#pragma unroll
            for (int mt = 0; mt < 4; mt++)
#pragma unroll
                for (int nt = 0; nt < 8; nt++)
                    mma_f16(d[mt][nt], afr[mt], bfr[nt]);
        }

        if (c + 3 < 32) issue((c + 3) & 3, c + 3);
        CP_COMMIT();
    }

    const int bm = blockIdx.y * 128;
    const int bn = blockIdx.x * 128;
#pragma unroll
    for (int mt = 0; mt < 4; mt++) {
        int row0 = bm + wm * 64 + mt * 16 + (lane >> 2);
#pragma unroll
        for (int nt = 0; nt < 8; nt++) {
            int col = bn + wn * 64 + nt * 8 + (lane & 3) * 2;
            float bx = bias[col], by = bias[col + 1];
            float2 v0 = make_float2(d[mt][nt][0] + bx, d[mt][nt][1] + by);
            float2 v1 = make_float2(d[mt][nt][2] + bx, d[mt][nt][3] + by);
            if (MODE == 0) {
                *(float2*)&out[(size_t)row0 * EE + col] = v0;
                *(float2*)&out[(size_t)(row0 + 8) * EE + col] = v1;
            } else {
                *(float2*)bhsd_addr(out, row0, col) = v0;
                *(float2*)bhsd_addr(out, row0 + 8, col) = v1;
            }
        }
    }
}

// ---------------------------------------------------------------------------
// prep: RoPE(Q,K) + fp16 panel build for Q/K/V.  Grid (32 tiles, 32 bh),
// 128 threads.  Q scaled by 1/sqrt(D)=0.125.
// ---------------------------------------------------------------------------
__global__ __launch_bounds__(128) void prep_kernel(
    const float* __restrict__ Q, const float* __restrict__ K,
    const float* __restrict__ V,
    uint32_t* __restrict__ Qh, uint32_t* __restrict__ Kh,
    uint32_t* __restrict__ Vh)
{
    const int tile = blockIdx.x;
    const int bh   = blockIdx.y;
    const int hb   = bh * SS * DD;
    const int s0   = tile * 64;
    const int t    = threadIdx.x;
    const int pbase = (bh * 32 + tile) * 2048;
    uint32_t* qp = Qh + pbase;
    uint32_t* kp = Kh + pbase;
    uint32_t* vp = Vh + pbase;

    // ---- Q, K with RoPE: thread -> (row = t>>1, i0 = (t&1)*16) ----
    {
        int row = t >> 1;
        int i0  = (t & 1) * 16;
        int s   = s0 + row;
        const float* qr = Q + hb + s * DD;
        const float* kr = K + hb + s * DD;
        float qlo[16], qhi[16], klo[16], khi[16];
#pragma unroll
        for (int u = 0; u < 4; u++) {
            *(float4*)&qlo[u*4] = *(const float4*)(qr + i0 + u*4);
            *(float4*)&qhi[u*4] = *(const float4*)(qr + i0 + 32 + u*4);
            *(float4*)&klo[u*4] = *(const float4*)(kr + i0 + u*4);
            *(float4*)&khi[u*4] = *(const float4*)(kr + i0 + 32 + u*4);
        }
        float q0v[16], q1v[16], k0v[16], k1v[16];
#pragma unroll
        for (int e = 0; e < 16; e++) {
            int i = i0 + e;
            float freq = exp2f(-(float)i * (13.287712379549449f / 32.0f));
            float sn, cs;
            sincosf((float)s * freq, &sn, &cs);
            float a = qlo[e] * 0.125f, b = qhi[e] * 0.125f;
            q0v[e] = a * cs - b * sn;
            q1v[e] = b * cs + a * sn;
            k0v[e] = klo[e] * cs - khi[e] * sn;
            k1v[e] = khi[e] * cs + klo[e] * sn;
        }
#pragma unroll
        for (int e = 0; e < 16; e += 2) {
            qp[q_slot(row, i0 + e)]      = pack_h2(q0v[e], q0v[e+1]);
            qp[q_slot(row, i0 + 32 + e)] = pack_h2(q1v[e], q1v[e+1]);
            kp[kv_slot(row, i0 + e)]      = pack_h2(k0v[e], k0v[e+1]);
            kp[kv_slot(row, i0 + 32 + e)] = pack_h2(k1v[e], k1v[e+1]);
        }
    }

    // ---- V: thread -> (row pair pr = t>>2, d0 = (t&3)*16); n=d, k=kv ----
    {
        int pr = t >> 2;
        int d0 = (t & 3) * 16;
        int r0 = pr * 2;
        const float* va = V + hb + (s0 + r0) * DD + d0;
        const float* vb = va + DD;
        float ra[16], rb[16];
#pragma unroll
        for (int u = 0; u < 4; u++) {
            *(float4*)&ra[u*4] = *(const float4*)(va + u*4);
            *(float4*)&rb[u*4] = *(const float4*)(vb + u*4);
        }
#pragma unroll
        for (int e = 0; e < 16; e++)
            vp[kv_slot(d0 + e, r0)] = pack_h2(ra[e], rb[e]);
    }
}

// ---------------------------------------------------------------------------
// Flash attention v2 (causal), fp16 m16n8k16, panel inputs + cp.async
// double-buffered K/V.  128 threads, Br=Bc=64.
// ---------------------------------------------------------------------------
#define ATTN_SMEM_BYTES ((2048 + 2*4096) * 4)   // 40 KB

__global__ __launch_bounds__(128) void attn_v2(
    const uint32_t* __restrict__ Qh, const uint32_t* __restrict__ Kh,
    const uint32_t* __restrict__ Vh, uint32_t* __restrict__ Aout)
{
    extern __shared__ uint32_t su[];
    const uint32_t sb = smem_u32(su);

    const int tid  = threadIdx.x;
    const int lane = tid & 31;
    const int w    = tid >> 5;

    const int iq = blockIdx.x;
    const int bh = blockIdx.y;
    const int q0 = iq * 64;

    const uint32_t* Qs = su;   // 2048 u32

    auto issue_kv = [&](int st, int j) {
        const uint4* gK = (const uint4*)(Kh + (size_t)(bh * 32 + j) * 2048);
        const uint4* gV = (const uint4*)(Vh + (size_t)(bh * 32 + j) * 2048);
        uint32_t sK = sb + (2048 + st * 4096) * 4;
        uint32_t sV = sK + 2048 * 4;
#pragma unroll
        for (int u = 0; u < 4; u++) {
            cp16(sK + (tid + u * 128) * 16, gK + tid + u * 128);
            cp16(sV + (tid + u * 128) * 16, gV + tid + u * 128);
        }
    };

    // prologue: Q tile + K/V tile 0 (one group)
    {
        const uint4* gQ = (const uint4*)(Qh + (size_t)(bh * 32 + iq) * 2048);
#pragma unroll
        for (int u = 0; u < 4; u++)
            cp16(sb + (tid + u * 128) * 16, gQ + tid + u * 128);
        issue_kv(0, 0);
        CP_COMMIT();
    }

    float o[8][4];
#pragma unroll
    for (int nt = 0; nt < 8; nt++)
#pragma unroll
        for (int e = 0; e < 4; e++) o[nt][e] = 0.f;
    float m0 = -1e30f, m1 = -1e30f, l0 = 0.f, l1 = 0.f;

    for (int j = 0; j <= iq; j++) {
        CP_WAIT0();
        __syncthreads();
        if (j < iq) { issue_kv((j + 1) & 1, j + 1); CP_COMMIT(); }

        const uint32_t* Ks = su + 2048 + (j & 1) * 4096;
        const uint32_t* Vs = Ks + 2048;

        // ---- S = Q K^T ----
        float s[8][4];
#pragma unroll
        for (int nt = 0; nt < 8; nt++)
#pragma unroll
            for (int e = 0; e < 4; e++) s[nt][e] = 0.f;
#pragma unroll
        for (int kt = 0; kt < 4; kt++) {
            uint32_t af[4];
            *(uint4*)af = *(const uint4*)(Qs + (w * 4 + kt) * 128 + lane * 4);
#pragma unroll
            for (int nt = 0; nt < 8; nt++) {
                uint32_t bf[2];
                *(uint2*)bf = *(const uint2*)(Ks + (nt * 4 + kt) * 64 + lane * 2);
                mma_f16(s[nt], af, bf);
            }
        }

        // ---- causal mask on diagonal tile ----
        if (j == iq) {
            int lr = w * 16 + (lane >> 2);
#pragma unroll
            for (int nt = 0; nt < 8; nt++) {
                int lc = nt * 8 + (lane & 3) * 2;
                if (lc > lr)     s[nt][0] = -1e30f;
                if (lc + 1 > lr) s[nt][1] = -1e30f;
                if (lc > lr + 8)     s[nt][2] = -1e30f;
                if (lc + 1 > lr + 8) s[nt][3] = -1e30f;
            }
        }

        // ---- online softmax ----
        float mx0 = m0, mx1 = m1;
#pragma unroll
        for (int nt = 0; nt < 8; nt++) {
            mx0 = fmaxf(mx0, fmaxf(s[nt][0], s[nt][1]));
            mx1 = fmaxf(mx1, fmaxf(s[nt][2], s[nt][3]));
        }
        mx0 = fmaxf(mx0, __shfl_xor_sync(0xffffffffu, mx0, 1));
        mx0 = fmaxf(mx0, __shfl_xor_sync(0xffffffffu, mx0, 2));
        mx1 = fmaxf(mx1, __shfl_xor_sync(0xffffffffu, mx1, 1));
        mx1 = fmaxf(mx1, __shfl_xor_sync(0xffffffffu, mx1, 2));
        float corr0 = __expf(m0 - mx0);
        float corr1 = __expf(m1 - mx1);
        m0 = mx0; m1 = mx1;

        uint32_t ap[4][4];
        float lp0 = 0.f, lp1 = 0.f;
#pragma unroll
        for (int nt = 0; nt < 8; nt++) {
            float p00 = __expf(s[nt][0] - mx0);
            float p01 = __expf(s[nt][1] - mx0);
            float p10 = __expf(s[nt][2] - mx1);
            float p11 = __expf(s[nt][3] - mx1);
            lp0 += p00 + p01;
            lp1 += p10 + p11;
            int kt = nt >> 1, h = (nt & 1) * 2;
            ap[kt][h]     = pack_h2(p00, p01);
            ap[kt][h + 1] = pack_h2(p10, p11);
        }
        lp0 += __shfl_xor_sync(0xffffffffu, lp0, 1);
        lp0 += __shfl_xor_sync(0xffffffffu, lp0, 2);
        lp1 += __shfl_xor_sync(0xffffffffu, lp1, 1);
        lp1 += __shfl_xor_sync(0xffffffffu, lp1, 2);
        l0 = l0 * corr0 + lp0;
        l1 = l1 * corr1 + lp1;

#pragma unroll
        for (int nt = 0; nt < 8; nt++) {
            o[nt][0] *= corr0; o[nt][1] *= corr0;
            o[nt][2] *= corr1; o[nt][3] *= corr1;
        }

        // ---- O += P @ V ----
#pragma unroll
        for (int kt = 0; kt < 4; kt++) {
#pragma unroll
            for (int nt = 0; nt < 8; nt++) {
                uint32_t bf[2];
                *(uint2*)bf = *(const uint2*)(Vs + (nt * 4 + kt) * 64 + lane * 2);
                mma_f16(o[nt], ap[kt], bf);
            }
        }
    }

    // ---- normalize + write fp16 A-panels ----
    float inv0 = 1.f / l0;
    float inv1 = 1.f / l1;
    int b_ = bh >> 4;
    int h_ = bh & 15;
    int grow = b_ * SS + q0 + w * 16 + (lane >> 2);
#pragma unroll
    for (int nt = 0; nt < 8; nt++) {
        int col = h_ * DD + nt * 8 + (lane & 3) * 2;
        Aout[a_slot(grow, col)]     = pack_h2(o[nt][0] * inv0, o[nt][1] * inv0);
        Aout[a_slot(grow + 8, col)] = pack_h2(o[nt][2] * inv1, o[nt][3] * inv1);
    }
}

// ---------------------------------------------------------------------------
extern "C" void kernel_launch(void* const* d_in, const int* in_sizes, int n_in,
                              void* d_out, int out_size)
{
    const float* x  = (const float*)d_in[0];
    // d_in[1] = mask (causal; structure known statically, unused)
    const float* Wq = (const float*)d_in[2];
    const float* bq = (const float*)d_in[3];
    const float* Wk = (const float*)d_in[4];
    const float* bk = (const float*)d_in[5];
    const float* Wv = (const float*)d_in[6];
    const float* bv = (const float*)d_in[7];
    const float* Wo = (const float*)d_in[8];
    const float* bo = (const float*)d_in[9];

    float *Qp, *Kp, *Vp;
    uint32_t *Xh, *Ah, *Qhp, *Khp, *Vhp;
    cudaGetSymbolAddress((void**)&Qp, g_Q);
    cudaGetSymbolAddress((void**)&Kp, g_K);
    cudaGetSymbolAddress((void**)&Vp, g_V);
    cudaGetSymbolAddress((void**)&Xh, g_Xh);
    cudaGetSymbolAddress((void**)&Ah, g_Ah);
    cudaGetSymbolAddress((void**)&Qhp, g_Qh);
    cudaGetSymbolAddress((void**)&Khp, g_Kh);
    cudaGetSymbolAddress((void**)&Vhp, g_Vh);

    cudaFuncSetAttribute(gemm_v4<0>,
                         cudaFuncAttributeMaxDynamicSharedMemorySize, GEMM_SMEM4);
    cudaFuncSetAttribute(gemm_v4<1>,
                         cudaFuncAttributeMaxDynamicSharedMemorySize, GEMM_SMEM4);
    cudaFuncSetAttribute(attn_v2,
                         cudaFuncAttributeMaxDynamicSharedMemorySize, ATTN_SMEM_BYTES);

    // fp32 -> fp16 panel conversions
    cvtA_kernel<<<MM * EE / 4 / 256, 256>>>(x, Xh);
    cvtB_kernel<<<dim3(EE * EE / 4 / 256, 1, 4), 256>>>(Wq, Wk, Wv, Wo);

    // QKV fused (z selects W panel / bias / output)
    gemm_v4<1><<<dim3(EE / 128, MM / 128, 3), 128, GEMM_SMEM4>>>(
        Xh, bq, bk, bv, Qp, Kp, Vp);

    // RoPE + fp16 panel build for attention
    prep_kernel<<<dim3(SS / 64, BB * HH), 128>>>(Qp, Kp, Vp, Qhp, Khp, Vhp);

    attn_v2<<<dim3(SS / 64, BB * HH), 128, ATTN_SMEM_BYTES>>>(Qhp, Khp, Vhp, Ah);

    // Output projection (uses Wo panel = g_Wh[3])
    gemm_v4<0><<<dim3(EE / 128, MM / 128, 1), 128, GEMM_SMEM4>>>(
        Ah, bo, bo, bo, (float*)d_out, nullptr, nullptr);
}